// round 12
// baseline (speedup 1.0000x reference)
#include <cuda_runtime.h>

// ShiftedWindowAttentionBlock: B=16, H=W=112, C=192, heads=6, hd=32, WS=7, SHIFT=3
// 112 % 7 == 0 -> no padding, reference applies no attention mask.
// One CTA per window (4096 windows), 512 threads, packed f32x2 FMA everywhere:
// k-packed FFMA2 GEMMs, phase 2 as a single flattened 18-tile pipeline
// (prefetch crosses chunk boundaries; epilogue inline at kbi==5),
// k-packed QK^T (588 half-tile items), packed PV, float2 LayerNorm,
// balanced m-mapping, cross-phase LDG prefetch (chunk-0 under phase 1,
// w_out under the 3c barrier), deferred softmax norm, padded smem strides.

#define CC      192
#define HEADS   6
#define HD      32
#define WSZ     7
#define LW      49
#define SHIFT_  3
#define IMG     112
#define THREADS 512
#define NCH     576         // 3*C (logical)
#define XSTR    200         // xA row stride (even, mod-32 = 8)
#define QSTR    584         // qkv row stride (even, 7*QSTR mod 32 = 24)

// dynamic smem layout (floats)
#define A_OFF   0                    // 49*200 = 9800   : xw (normalized), later attn_out
#define B_OFF   9800                 // 49*584 = 28616  : qkv
#define C_OFF   (9800 + 28616)       // 6*49*49 = 14406 : scores / 2x weight buf [192][34]
#define WS_STRIDE 34                 // per-n row of 32 kk + pad2; LDS.64/STS conflict-free
#define WBUF_SZ  (CC * WS_STRIDE)    // 6528 floats per buffer (x2 = 13056 <= 14406)
#define SMEM_FLOATS (9800 + 28616 + 14406)
#define SMEM_BYTES  (SMEM_FLOATS * 4)   // 211,288 B < 227 KB cap

typedef unsigned long long ull;

__device__ __forceinline__ ull pack2(float a, float b) {
    ull r; asm("mov.b64 %0, {%1, %2};" : "=l"(r) : "f"(a), "f"(b)); return r;
}
__device__ __forceinline__ void ffma2(ull& d, ull a, ull b) {
    asm("fma.rn.f32x2 %0, %1, %2, %0;" : "+l"(d) : "l"(a), "l"(b));
}
__device__ __forceinline__ ull fmul2(ull a, ull b) {
    ull r; asm("mul.rn.f32x2 %0, %1, %2;" : "=l"(r) : "l"(a), "l"(b)); return r;
}
__device__ __forceinline__ float2 unpack2(ull v) {
    float2 f; asm("mov.b64 {%0, %1}, %2;" : "=f"(f.x), "=f"(f.y) : "l"(v)); return f;
}

// One 32-wide k-tile, k-packed: MR rows (m = wid + 16*i), 6 single columns
// n = ng + 32*t. acc[i][t] holds (even-k partial, odd-k partial).
template<int MR>
__device__ __forceinline__ void gemm_tile(ull (&acc)[4][6],
                                          const float* __restrict__ xrow, // xA + wid*XSTR + kb
                                          const float* __restrict__ wsm,  // staged [CC][WS_STRIDE]
                                          int ng)
{
    #pragma unroll
    for (int kk = 0; kk < 32; kk += 2) {
        ull aa[MR];
        #pragma unroll
        for (int i = 0; i < MR; i++)
            aa[i] = *(const ull*)&xrow[i * 16 * XSTR + kk];   // broadcast LDS.64 (a_k, a_k1)
        ull ww[6];
        #pragma unroll
        for (int t = 0; t < 6; t++)
            ww[t] = *(const ull*)&wsm[(ng + 32 * t) * WS_STRIDE + kk];
        #pragma unroll
        for (int i = 0; i < MR; i++)
            #pragma unroll
            for (int t = 0; t < 6; t++)
                ffma2(acc[i][t], aa[i], ww[t]);
    }
}

// One kt-column half of a 7x7 QK^T tile, k-packed over HD.
template<int JN>
__device__ __forceinline__ void qk_half(float* __restrict__ sp,      // sC row base + j offset
                                        const float* __restrict__ qp, // q tile base
                                        const float* __restrict__ kp) // k tile base (+ half*4*QSTR)
{
    ull acc2[7][JN];
    #pragma unroll
    for (int i = 0; i < 7; i++)
        #pragma unroll
        for (int j = 0; j < JN; j++) acc2[i][j] = pack2(0.f, 0.f);
    #pragma unroll 4
    for (int k = 0; k < HD; k += 2) {
        ull qv[7], kv[JN];
        #pragma unroll
        for (int i = 0; i < 7; i++) qv[i] = *(const ull*)&qp[i * QSTR + k];
        #pragma unroll
        for (int j = 0; j < JN; j++) kv[j] = *(const ull*)&kp[j * QSTR + k];
        #pragma unroll
        for (int i = 0; i < 7; i++)
            #pragma unroll
            for (int j = 0; j < JN; j++)
                ffma2(acc2[i][j], qv[i], kv[j]);
    }
    #pragma unroll
    for (int i = 0; i < 7; i++)
        #pragma unroll
        for (int j = 0; j < JN; j++) {
            float2 s = unpack2(acc2[i][j]);
            sp[i * 49 + j] = s.x + s.y;
        }
}

__global__ __launch_bounds__(THREADS, 1)
void swin_attn_kernel(const float* __restrict__ x,
                      const float* __restrict__ w_qkv,
                      const float* __restrict__ b_qkv,
                      const float* __restrict__ w_out,
                      const float* __restrict__ b_out,
                      const float* __restrict__ gamma,
                      const float* __restrict__ beta,
                      float* __restrict__ out)
{
    extern __shared__ float sm[];
    float* xA  = sm + A_OFF;   // [49][XSTR]
    float* qkv = sm + B_OFF;   // [49][QSTR]
    float* sC  = sm + C_OFF;   // scores [6][49][49]  / weight double-buffer
    __shared__ int   gbase[LW];
    __shared__ float sinv[HEADS * LW];   // per-(head,row) 1/sum for deferred softmax norm

    const int tid  = threadIdx.x;
    const int win  = blockIdx.x;
    const int b    = win >> 8;
    const int wh   = (win >> 4) & 15;
    const int ww   = win & 15;

    const int wid  = tid >> 5;   // 0..15
    const int lane = tid & 31;

    float* wbuf0 = sC;
    float* wbuf1 = sC + WBUF_SZ;
    const int pn_base = wid;     // staged n = wid + 16*j (j<12), kk = lane
    const int pk = lane;

    // ---- Prefetch phase-2 tile 0 weights: LDG issued NOW, flies under phase 1 ----
    float pre0[12];
    #pragma unroll
    for (int j = 0; j < 12; j++)
        pre0[j] = w_qkv[(pn_base + 16 * j) * CC + pk];

    // ---------------- Phase 1: gather (shifted) + LayerNorm, float2 ----------------
    for (int t = wid; t < LW; t += 16) {
        int r  = t / WSZ, c = t % WSZ;
        int hh = (wh * WSZ + r + SHIFT_) % IMG;
        int wc = (ww * WSZ + c + SHIFT_) % IMG;
        int gb = ((b * IMG + hh) * IMG + wc) * CC;
        if (lane == 0) gbase[t] = gb;
        const float2* xp = (const float2*)(x + gb);   // gb = 192*idx -> 8B aligned
        float2 v[3];
        float s = 0.f, s2 = 0.f;
        #pragma unroll
        for (int j = 0; j < 3; j++) {
            v[j] = xp[lane + 32 * j];
            s  += v[j].x + v[j].y;
            s2 += v[j].x * v[j].x + v[j].y * v[j].y;
        }
        #pragma unroll
        for (int o = 16; o > 0; o >>= 1) {
            s  += __shfl_xor_sync(0xffffffffu, s,  o);
            s2 += __shfl_xor_sync(0xffffffffu, s2, o);
        }
        float mean = s * (1.f / CC);
        float var  = s2 * (1.f / CC) - mean * mean;
        float rstd = rsqrtf(var + 1e-5f);
        #pragma unroll
        for (int j = 0; j < 3; j++) {
            int k2 = lane + 32 * j;                    // float2 index; 2*k2 float offset
            float2 g  = ((const float2*)gamma)[k2];
            float2 be = ((const float2*)beta)[k2];
            float2 o2;
            o2.x = (v[j].x - mean) * rstd * g.x + be.x;
            o2.y = (v[j].y - mean) * rstd * g.y + be.y;
            *(float2*)&xA[t * XSTR + 2 * k2] = o2;     // XSTR even -> aligned
        }
    }
    // stage prefetched tile-0 weights (sC untouched by phase 1)
    #pragma unroll
    for (int j = 0; j < 12; j++)
        wbuf0[(pn_base + 16 * j) * WS_STRIDE + pk] = pre0[j];
    __syncthreads();   // covers xA AND wbuf0

    // ---------------- Phase 2: QKV projection, flattened 18-tile pipeline ----------------
    // warp wid: rows {wid, wid+16, wid+32} (+ row 48 on warp 0);
    // lane: 6 single columns n = lane + 32t per chunk. Prefetch crosses
    // chunk boundaries; per-chunk epilogue inline at kbi==5.
    {
        const int ng = lane;
        float* wbuf[2] = { wbuf0, wbuf1 };
        const int nr = (wid == 0) ? 4 : 3;

        ull acc[4][6];
        #pragma unroll
        for (int i = 0; i < 4; i++)
            #pragma unroll
            for (int t = 0; t < 6; t++) acc[i][t] = pack2(0.f, 0.f);

        int cur = 0;
        for (int ti = 0; ti < 18; ti++) {
            const int chunk = ti / 6;
            const int kbi   = ti % 6;
            const int kb    = kbi * 32;

            float pre[12];
            if (ti < 17) {
                const int nti = ti + 1;
                const float* Wn = w_qkv + (nti / 6) * CC * CC + (nti % 6) * 32;
                #pragma unroll
                for (int j = 0; j < 12; j++)
                    pre[j] = Wn[(pn_base + 16 * j) * CC + pk];
            }

            const float* xrow = xA + wid * XSTR + kb;
            if (wid == 0) gemm_tile<4>(acc, xrow, wbuf[cur], ng);
            else          gemm_tile<3>(acc, xrow, wbuf[cur], ng);

            if (kbi == 5) {   // chunk epilogue: write q/k/v slice, reset acc
                const int nbase = chunk * CC;
                for (int i = 0; i < nr; i++) {
                    int m = wid + 16 * i;
                    #pragma unroll
                    for (int t = 0; t < 6; t++) {
                        int n = nbase + ng + 32 * t;
                        float2 s2v = unpack2(acc[i][t]);
                        qkv[m * QSTR + n] = s2v.x + s2v.y + b_qkv[n];
                        acc[i][t] = pack2(0.f, 0.f);
                    }
                }
            }

            if (ti < 17) {
                float* dst = wbuf[cur ^ 1];
                #pragma unroll
                for (int j = 0; j < 12; j++)
                    dst[(pn_base + 16 * j) * WS_STRIDE + pk] = pre[j];
            }
            __syncthreads();
            cur ^= 1;
        }
    }

    // ---------------- Phase 3a: S = Q K^T, 588 half-tile items (all warps busy) ----------------
    for (int tt = tid; tt < HEADS * 49 * 2; tt += THREADS) {   // 588 items
        int half = tt & 1;
        int tile = tt >> 1;            // 0..293
        int h    = tile / 49;
        int rem  = tile % 49;
        int qt   = rem / 7, kt = rem % 7;
        const float* qp = qkv + (qt * 7) * QSTR + h * HD;
        const float* kp = qkv + (kt * 7) * QSTR + CC + h * HD;
        float* sp = sC + h * 2401 + (qt * 7) * 49 + kt * 7;
        if (half == 0) qk_half<4>(sp,     qp, kp);
        else           qk_half<3>(sp + 4, qp, kp + 4 * QSTR);
    }
    __syncthreads();

    // ---------------- Phase 3b: softmax rows (scale 1/sqrt(32)); norm deferred ----------------
    {
        const float scale = 0.1767766952966369f;
        for (int r = tid; r < HEADS * LW; r += THREADS) {
            float* row = sC + (r / LW) * 2401 + (r % LW) * 49;
            float mx = -1e30f;
            for (int j = 0; j < LW; j++) mx = fmaxf(mx, row[j]);
            float ssum = 0.f;
            for (int j = 0; j < LW; j++) {
                float e = __expf((row[j] - mx) * scale);
                row[j] = e;
                ssum += e;
            }
            sinv[r] = 1.f / ssum;   // applied in PV epilogue
        }
    }
    __syncthreads();

    // ---------------- Phase 3c: O = (exp(S) V) * inv, 336 tiles of 7q x (2 d-pairs) ----------------
    for (int tt = tid; tt < HEADS * 7 * 8; tt += THREADS) {  // 336 tiles
        int h   = tt / 56;
        int rem = tt % 56;
        int qt  = rem / 8, dg = rem % 8;                      // dg: 4-float group
        ull acc[7][2];
        #pragma unroll
        for (int i = 0; i < 7; i++)
            #pragma unroll
            for (int d = 0; d < 2; d++) acc[i][d] = pack2(0.f, 0.f);
        const float* pp = sC + h * 2401 + (qt * 7) * 49;
        const float* vp = qkv + 2 * CC + h * HD + dg * 4;     // even offset -> 8B aligned
        #pragma unroll 7
        for (int k = 0; k < LW; k++) {
            ull pv[7];
            #pragma unroll
            for (int i = 0; i < 7; i++) {
                float p = pp[i * 49 + k];
                pv[i] = pack2(p, p);
            }
            const float* vr = vp + k * QSTR;
            ull v0 = *(const ull*)(vr);
            ull v1 = *(const ull*)(vr + 2);
            #pragma unroll
            for (int i = 0; i < 7; i++) {
                ffma2(acc[i][0], pv[i], v0);
                ffma2(acc[i][1], pv[i], v1);
            }
        }
        #pragma unroll
        for (int i = 0; i < 7; i++) {
            float inv = sinv[h * LW + qt * 7 + i];
            ull iv = pack2(inv, inv);
            #pragma unroll
            for (int d = 0; d < 2; d++)
                *(float2*)&xA[(qt * 7 + i) * XSTR + h * HD + dg * 4 + 2 * d]
                    = unpack2(fmul2(acc[i][d], iv));
        }
    }

    // ---- Prefetch phase-4 weights: LDG issued before the 3c barrier ----
    float pre4[12];
    #pragma unroll
    for (int j = 0; j < 12; j++)
        pre4[j] = w_out[(pn_base + 16 * j) * CC + pk];
    __syncthreads();   // end of 3c; pre4 LDGs drain behind the barrier

    // ---------------- Phase 4: out proj (49x192x192) + residual + scatter ----------------
    {
        const int ng = lane;
        float* wbuf[2] = { wbuf0, wbuf1 };

        ull acc[4][6];
        #pragma unroll
        for (int i = 0; i < 4; i++)
            #pragma unroll
            for (int t = 0; t < 6; t++) acc[i][t] = pack2(0.f, 0.f);

        // stage prefetched kb=0 tile (scores consumed in 3c)
        #pragma unroll
        for (int j = 0; j < 12; j++)
            wbuf[0][(pn_base + 16 * j) * WS_STRIDE + pk] = pre4[j];
        __syncthreads();

        int cur = 0;
        for (int kbi = 0; kbi < 6; kbi++) {
            const int kb = kbi * 32;
            float pre[12];
            if (kbi < 5) {
                #pragma unroll
                for (int j = 0; j < 12; j++) {
                    int n = pn_base + 16 * j;
                    pre[j] = w_out[n * CC + (kb + 32) + pk];
                }
            }
            const float* xrow = xA + wid * XSTR + kb;
            if (wid == 0) gemm_tile<4>(acc, xrow, wbuf[cur], ng);
            else          gemm_tile<3>(acc, xrow, wbuf[cur], ng);
            if (kbi < 5) {
                float* dst = wbuf[cur ^ 1];
                #pragma unroll
                for (int j = 0; j < 12; j++)
                    dst[(pn_base + 16 * j) * WS_STRIDE + pk] = pre[j];
            }
            __syncthreads();
            cur ^= 1;
        }

        const int nr = (wid == 0) ? 4 : 3;
        for (int i = 0; i < nr; i++) {
            int m = wid + 16 * i;
            int gb = gbase[m];
            #pragma unroll
            for (int t = 0; t < 6; t++) {
                int n = ng + 32 * t;
                float2 s2v = unpack2(acc[i][t]);
                out[gb + n] = x[gb + n] + s2v.x + s2v.y + b_out[n];
            }
        }
    }
}

extern "C" void kernel_launch(void* const* d_in, const int* in_sizes, int n_in,
                              void* d_out, int out_size)
{
    const float* x     = (const float*)d_in[0];
    const float* w_qkv = (const float*)d_in[1];
    const float* b_qkv = (const float*)d_in[2];
    const float* w_out = (const float*)d_in[3];
    const float* b_out = (const float*)d_in[4];
    const float* gamma = (const float*)d_in[5];
    const float* beta  = (const float*)d_in[6];
    float* out = (float*)d_out;

    cudaFuncSetAttribute(swin_attn_kernel,
                         cudaFuncAttributeMaxDynamicSharedMemorySize, SMEM_BYTES);

    swin_attn_kernel<<<4096, THREADS, SMEM_BYTES>>>(
        x, w_qkv, b_qkv, w_out, b_out, gamma, beta, out);
}

// round 16
// speedup vs baseline: 1.4081x; 1.4081x over previous
#include <cuda_runtime.h>

// ShiftedWindowAttentionBlock: B=16, H=W=112, C=192, heads=6, hd=32, WS=7, SHIFT=3
// One CTA per window (4096), 512 threads. R16 = R15 (8x2 warp grid + LDS.128 in
// phases 2/4 + LDS.128 V in 3c; targets the measured L1=67% crossbar bound)
// plus padded score stride 49->50 enabling paired LDS.64 P-loads in phase 3c.

#define CC      192
#define HEADS   6
#define HD      32
#define WSZ     7
#define LW      49
#define SHIFT_  3
#define IMG     112
#define THREADS 512
#define NCH     576
#define XSTR    200         // xA row stride (mod4=0 -> 16B-aligned k-quads)
#define QSTR    584         // qkv row stride (mod4=0)
#define SSTR    50          // score row stride (even -> LDS.64 P pairs)
#define SHSZ    (LW * SSTR) // 2450 floats per head

#define A_OFF   0                    // 49*200 = 9800
#define B_OFF   9800                 // 49*584 = 28616
#define C_OFF   (9800 + 28616)       // 6*2450 = 14700: scores / 2x weight buf [192][36]
#define WS_STRIDE 36                 // mod4=0: LDS.128-capable, conflict-free
#define WBUF_SZ  (CC * WS_STRIDE)    // 6912 x2 = 13824 <= 14700
#define SMEM_FLOATS (9800 + 28616 + 14700)
#define SMEM_BYTES  (SMEM_FLOATS * 4)   // 212,464 B < 227 KB cap

typedef unsigned long long ull;

__device__ __forceinline__ ull pack2(float a, float b) {
    ull r; asm("mov.b64 %0, {%1, %2};" : "=l"(r) : "f"(a), "f"(b)); return r;
}
__device__ __forceinline__ void ffma2(ull& d, ull a, ull b) {
    asm("fma.rn.f32x2 %0, %1, %2, %0;" : "+l"(d) : "l"(a), "l"(b));
}
__device__ __forceinline__ ull fmul2(ull a, ull b) {
    ull r; asm("mul.rn.f32x2 %0, %1, %2;" : "=l"(r) : "l"(a), "l"(b)); return r;
}
__device__ __forceinline__ float2 unpack2(ull v) {
    float2 f; asm("mov.b64 {%0, %1}, %2;" : "=f"(f.x), "=f"(f.y) : "l"(v)); return f;
}

// One 32-wide k-tile, 8x2 grid: MR rows (m = rg + 8*i), 3 cols (colbase + 32*t).
// LDS.128 on both operands; acc[i][t] = (sum of even ks, sum of odd ks).
template<int MR>
__device__ __forceinline__ void gemm_tile(ull (&acc)[7][3],
                                          const float* __restrict__ xrow, // xA + rg*XSTR + kb
                                          const float* __restrict__ wsm,  // staged [192][36]
                                          int colbase)                    // cg*96 + lane
{
    #pragma unroll
    for (int kk = 0; kk < 32; kk += 4) {
        ull alo[MR], ahi[MR];
        #pragma unroll
        for (int i = 0; i < MR; i++) {
            longlong2 a4 = *(const longlong2*)&xrow[i * 8 * XSTR + kk];  // 16B broadcast
            alo[i] = (ull)a4.x; ahi[i] = (ull)a4.y;
        }
        ull wlo[3], whi[3];
        #pragma unroll
        for (int t = 0; t < 3; t++) {
            longlong2 w4 = *(const longlong2*)&wsm[(colbase + 32 * t) * WS_STRIDE + kk];
            wlo[t] = (ull)w4.x; whi[t] = (ull)w4.y;
        }
        #pragma unroll
        for (int i = 0; i < MR; i++)
            #pragma unroll
            for (int t = 0; t < 3; t++) {
                ffma2(acc[i][t], alo[i], wlo[t]);
                ffma2(acc[i][t], ahi[i], whi[t]);
            }
    }
}

// One kt-column half of a 7x7 QK^T tile, k-packed over HD. Scores at stride SSTR.
template<int JN>
__device__ __forceinline__ void qk_half(float* __restrict__ sp,
                                        const float* __restrict__ qp,
                                        const float* __restrict__ kp)
{
    ull acc2[7][JN];
    #pragma unroll
    for (int i = 0; i < 7; i++)
        #pragma unroll
        for (int j = 0; j < JN; j++) acc2[i][j] = pack2(0.f, 0.f);
    #pragma unroll 4
    for (int k = 0; k < HD; k += 2) {
        ull qv[7], kv[JN];
        #pragma unroll
        for (int i = 0; i < 7; i++) qv[i] = *(const ull*)&qp[i * QSTR + k];
        #pragma unroll
        for (int j = 0; j < JN; j++) kv[j] = *(const ull*)&kp[j * QSTR + k];
        #pragma unroll
        for (int i = 0; i < 7; i++)
            #pragma unroll
            for (int j = 0; j < JN; j++)
                ffma2(acc2[i][j], qv[i], kv[j]);
    }
    #pragma unroll
    for (int i = 0; i < 7; i++)
        #pragma unroll
        for (int j = 0; j < JN; j++) {
            float2 s = unpack2(acc2[i][j]);
            sp[i * SSTR + j] = s.x + s.y;
        }
}

__global__ __launch_bounds__(THREADS, 1)
void swin_attn_kernel(const float* __restrict__ x,
                      const float* __restrict__ w_qkv,
                      const float* __restrict__ b_qkv,
                      const float* __restrict__ w_out,
                      const float* __restrict__ b_out,
                      const float* __restrict__ gamma,
                      const float* __restrict__ beta,
                      float* __restrict__ out)
{
    extern __shared__ float sm[];
    float* xA  = sm + A_OFF;   // [49][XSTR]
    float* qkv = sm + B_OFF;   // [49][QSTR]
    float* sC  = sm + C_OFF;   // scores [6][49][SSTR] / weight double-buffer
    __shared__ int   gbase[LW];
    __shared__ float sinv[HEADS * LW];

    const int tid  = threadIdx.x;
    const int win  = blockIdx.x;
    const int b    = win >> 8;
    const int wh   = (win >> 4) & 15;
    const int ww   = win & 15;

    const int wid  = tid >> 5;   // 0..15
    const int lane = tid & 31;
    const int rg   = wid & 7;    // row group (rows rg + 8i)
    const int cg   = wid >> 3;   // col group (cols cg*96 ..)
    const int MRw  = (rg == 0) ? 7 : 6;

    float* wbuf0 = sC;
    float* wbuf1 = sC + WBUF_SZ;
    const int pn_base = wid;     // staged n = wid + 16*j (j<12), kk = lane
    const int pk = lane;

    // ---- Prefetch phase-2 tile 0 weights (fly under phase 1) ----
    float pre0[12];
    #pragma unroll
    for (int j = 0; j < 12; j++)
        pre0[j] = w_qkv[(pn_base + 16 * j) * CC + pk];

    // ---------------- Phase 1: gather (shifted) + LayerNorm, float2 ----------------
    for (int t = wid; t < LW; t += 16) {
        int r  = t / WSZ, c = t % WSZ;
        int hh = (wh * WSZ + r + SHIFT_) % IMG;
        int wc = (ww * WSZ + c + SHIFT_) % IMG;
        int gb = ((b * IMG + hh) * IMG + wc) * CC;
        if (lane == 0) gbase[t] = gb;
        const float2* xp = (const float2*)(x + gb);
        float2 v[3];
        float s = 0.f, s2 = 0.f;
        #pragma unroll
        for (int j = 0; j < 3; j++) {
            v[j] = xp[lane + 32 * j];
            s  += v[j].x + v[j].y;
            s2 += v[j].x * v[j].x + v[j].y * v[j].y;
        }
        #pragma unroll
        for (int o = 16; o > 0; o >>= 1) {
            s  += __shfl_xor_sync(0xffffffffu, s,  o);
            s2 += __shfl_xor_sync(0xffffffffu, s2, o);
        }
        float mean = s * (1.f / CC);
        float var  = s2 * (1.f / CC) - mean * mean;
        float rstd = rsqrtf(var + 1e-5f);
        #pragma unroll
        for (int j = 0; j < 3; j++) {
            int k2 = lane + 32 * j;
            float2 g  = ((const float2*)gamma)[k2];
            float2 be = ((const float2*)beta)[k2];
            float2 o2;
            o2.x = (v[j].x - mean) * rstd * g.x + be.x;
            o2.y = (v[j].y - mean) * rstd * g.y + be.y;
            *(float2*)&xA[t * XSTR + 2 * k2] = o2;
        }
    }
    #pragma unroll
    for (int j = 0; j < 12; j++)
        wbuf0[(pn_base + 16 * j) * WS_STRIDE + pk] = pre0[j];
    __syncthreads();

    // ---------------- Phase 2: QKV projection, flattened 18-tile pipeline ----------------
    {
        const int colbase = cg * 96 + lane;
        float* wbuf[2] = { wbuf0, wbuf1 };

        ull acc[7][3];
        #pragma unroll
        for (int i = 0; i < 7; i++)
            #pragma unroll
            for (int t = 0; t < 3; t++) acc[i][t] = pack2(0.f, 0.f);

        int cur = 0;
        for (int ti = 0; ti < 18; ti++) {
            const int chunk = ti / 6;
            const int kbi   = ti % 6;
            const int kb    = kbi * 32;

            float pre[12];
            if (ti < 17) {
                const int nti = ti + 1;
                const float* Wn = w_qkv + (nti / 6) * CC * CC + (nti % 6) * 32;
                #pragma unroll
                for (int j = 0; j < 12; j++)
                    pre[j] = Wn[(pn_base + 16 * j) * CC + pk];
            }

            const float* xrow = xA + rg * XSTR + kb;
            if (rg == 0) gemm_tile<7>(acc, xrow, wbuf[cur], colbase);
            else         gemm_tile<6>(acc, xrow, wbuf[cur], colbase);

            if (kbi == 5) {   // chunk epilogue
                const int nbase = chunk * CC;
                for (int i = 0; i < MRw; i++) {
                    int m = rg + 8 * i;
                    #pragma unroll
                    for (int t = 0; t < 3; t++) {
                        int n = nbase + colbase + 32 * t;
                        float2 s2v = unpack2(acc[i][t]);
                        qkv[m * QSTR + n] = s2v.x + s2v.y + b_qkv[n];
                        acc[i][t] = pack2(0.f, 0.f);
                    }
                }
            }

            if (ti < 17) {
                float* dst = wbuf[cur ^ 1];
                #pragma unroll
                for (int j = 0; j < 12; j++)
                    dst[(pn_base + 16 * j) * WS_STRIDE + pk] = pre[j];
            }
            __syncthreads();
            cur ^= 1;
        }
    }

    // ---------------- Phase 3a: S = Q K^T, 588 half-tile items ----------------
    for (int tt = tid; tt < HEADS * 49 * 2; tt += THREADS) {
        int half = tt & 1;
        int tile = tt >> 1;
        int h    = tile / 49;
        int rem  = tile % 49;
        int qt   = rem / 7, kt = rem % 7;
        const float* qp = qkv + (qt * 7) * QSTR + h * HD;
        const float* kp = qkv + (kt * 7) * QSTR + CC + h * HD;
        float* sp = sC + h * SHSZ + (qt * 7) * SSTR + kt * 7;
        if (half == 0) qk_half<4>(sp,     qp, kp);
        else           qk_half<3>(sp + 4, qp, kp + 4 * QSTR);
    }
    __syncthreads();

    // ---------------- Phase 3b: softmax rows; norm deferred ----------------
    {
        const float scale = 0.1767766952966369f;
        for (int r = tid; r < HEADS * LW; r += THREADS) {
            float* row = sC + (r / LW) * SHSZ + (r % LW) * SSTR;
            float mx = -1e30f;
            for (int j = 0; j < LW; j++) mx = fmaxf(mx, row[j]);
            float ssum = 0.f;
            for (int j = 0; j < LW; j++) {
                float e = __expf((row[j] - mx) * scale);
                row[j] = e;
                ssum += e;
            }
            sinv[r] = 1.f / ssum;
        }
    }
    __syncthreads();

    // ---------------- Phase 3c: O = (exp(S) V) * inv, 336 tiles ----------------
    // Paired k-steps: LDS.64 P pairs (even SSTR => aligned), LDS.128 V rows.
    for (int tt = tid; tt < HEADS * 7 * 8; tt += THREADS) {
        int h   = tt / 56;
        int rem = tt % 56;
        int qt  = rem / 8, dg = rem % 8;
        ull acc[7][2];
        #pragma unroll
        for (int i = 0; i < 7; i++)
            #pragma unroll
            for (int d = 0; d < 2; d++) acc[i][d] = pack2(0.f, 0.f);
        const float* pp = sC + h * SHSZ + (qt * 7) * SSTR;
        const float* vp = qkv + 2 * CC + h * HD + dg * 4;   // 16B aligned
        #pragma unroll 6
        for (int k = 0; k < LW - 1; k += 2) {
            ull pd[7];
            #pragma unroll
            for (int i = 0; i < 7; i++)
                pd[i] = *(const ull*)&pp[i * SSTR + k];      // (p_k, p_k1)
            longlong2 va = *(const longlong2*)(vp + k * QSTR);
            longlong2 vb = *(const longlong2*)(vp + (k + 1) * QSTR);
            ull va0 = (ull)va.x, va1 = (ull)va.y;
            ull vb0 = (ull)vb.x, vb1 = (ull)vb.y;
            #pragma unroll
            for (int i = 0; i < 7; i++) {
                float2 p2 = unpack2(pd[i]);
                ull p0 = pack2(p2.x, p2.x);
                ull p1 = pack2(p2.y, p2.y);
                ffma2(acc[i][0], p0, va0);
                ffma2(acc[i][1], p0, va1);
                ffma2(acc[i][0], p1, vb0);
                ffma2(acc[i][1], p1, vb1);
            }
        }
        {   // tail k = 48
            const int k = LW - 1;
            longlong2 v4 = *(const longlong2*)(vp + k * QSTR);
            ull v0 = (ull)v4.x, v1 = (ull)v4.y;
            #pragma unroll
            for (int i = 0; i < 7; i++) {
                float p = pp[i * SSTR + k];
                ull ps = pack2(p, p);
                ffma2(acc[i][0], ps, v0);
                ffma2(acc[i][1], ps, v1);
            }
        }
        #pragma unroll
        for (int i = 0; i < 7; i++) {
            float inv = sinv[h * LW + qt * 7 + i];
            ull iv = pack2(inv, inv);
            #pragma unroll
            for (int d = 0; d < 2; d++)
                *(float2*)&xA[(qt * 7 + i) * XSTR + h * HD + dg * 4 + 2 * d]
                    = unpack2(fmul2(acc[i][d], iv));
        }
    }

    // ---- Prefetch phase-4 weights before the 3c barrier ----
    float pre4[12];
    #pragma unroll
    for (int j = 0; j < 12; j++)
        pre4[j] = w_out[(pn_base + 16 * j) * CC + pk];
    __syncthreads();

    // ---------------- Phase 4: out proj + residual + scatter ----------------
    {
        const int colbase = cg * 96 + lane;
        float* wbuf[2] = { wbuf0, wbuf1 };

        ull acc[7][3];
        #pragma unroll
        for (int i = 0; i < 7; i++)
            #pragma unroll
            for (int t = 0; t < 3; t++) acc[i][t] = pack2(0.f, 0.f);

        #pragma unroll
        for (int j = 0; j < 12; j++)
            wbuf[0][(pn_base + 16 * j) * WS_STRIDE + pk] = pre4[j];
        __syncthreads();

        int cur = 0;
        for (int kbi = 0; kbi < 6; kbi++) {
            const int kb = kbi * 32;
            float pre[12];
            if (kbi < 5) {
                #pragma unroll
                for (int j = 0; j < 12; j++)
                    pre[j] = w_out[(pn_base + 16 * j) * CC + (kb + 32) + pk];
            }
            const float* xrow = xA + rg * XSTR + kb;
            if (rg == 0) gemm_tile<7>(acc, xrow, wbuf[cur], colbase);
            else         gemm_tile<6>(acc, xrow, wbuf[cur], colbase);
            if (kbi < 5) {
                float* dst = wbuf[cur ^ 1];
                #pragma unroll
                for (int j = 0; j < 12; j++)
                    dst[(pn_base + 16 * j) * WS_STRIDE + pk] = pre[j];
            }
            __syncthreads();
            cur ^= 1;
        }

        for (int i = 0; i < MRw; i++) {
            int m = rg + 8 * i;
            int gb = gbase[m];
            #pragma unroll
            for (int t = 0; t < 3; t++) {
                int n = colbase + 32 * t;
                float2 s2v = unpack2(acc[i][t]);
                out[gb + n] = x[gb + n] + s2v.x + s2v.y + b_out[n];
            }
        }
    }
}

extern "C" void kernel_launch(void* const* d_in, const int* in_sizes, int n_in,
                              void* d_out, int out_size)
{
    const float* x     = (const float*)d_in[0];
    const float* w_qkv = (const float*)d_in[1];
    const float* b_qkv = (const float*)d_in[2];
    const float* w_out = (const float*)d_in[3];
    const float* b_out = (const float*)d_in[4];
    const float* gamma = (const float*)d_in[5];
    const float* beta  = (const float*)d_in[6];
    float* out = (float*)d_out;

    cudaFuncSetAttribute(swin_attn_kernel,
                         cudaFuncAttributeMaxDynamicSharedMemorySize, SMEM_BYTES);

    swin_attn_kernel<<<4096, THREADS, SMEM_BYTES>>>(
        x, w_qkv, b_qkv, w_out, b_out, gamma, beta, out);
}